// round 7
// baseline (speedup 1.0000x reference)
#include <cuda_runtime.h>
#include <cstdint>

#define HPAD   66
#define CIN    128
#define OC     128
#define HW     4096
#define NB     4
#define NS     9
#define NCHUNK 36
#define STAGES 4

// ---- device scratch ----
__device__ float  g_xpad[NB * HPAD * HPAD * CIN + 64];  // NHWC padded x (+pad for safe OOB)
__device__ float  g_wk2[NS * OC * CIN];                 // [n][oc][c], tf32-rounded
__device__ float4 g_gw[NB * NS * HW];                   // bilinear weights
__device__ int4   g_gi[NB * NS * HW];                   // gather indices (66x66 plane)

// ---- dynamic smem layout (bytes) ----
#define SM_TPTR   0
#define SM_FULL(s)  (16 + 8 * (s))
#define SM_EMPTY(s) (64 + 8 * (s))
#define SM_A(s)   (1024 + (s) * 32768)
#define SM_B(s)   (SM_A(s) + 16384)
#define SM_TS     1024               /* aliases stage 0: free when epilogue runs */
#define SM_TOTAL  (1024 + STAGES * 32768)

#define TMEM_COLS 128
// idesc kind::tf32: dtype=F32(1)<<4, atype=TF32(2)<<7, btype=TF32(2)<<10,
// N>>3 (16)<<17, M>>4 (8)<<24
#define IDESC 0x8200910u

#define SW128(o) ((o) ^ (((o) >> 3) & 0x70))

// Feature gate: tcgen05 only exists in the compute_103a device pass.
#if !defined(__CUDA_ARCH__) || defined(__CUDA_ARCH_FEAT_SM103_ALL)
#define HAS_TCGEN05 1
#else
#define HAS_TCGEN05 0
#endif

// ---------------- PTX helpers ----------------
__device__ __forceinline__ uint32_t smem_u32(const void* p) {
    uint32_t a;
    asm("{ .reg .u64 t; cvta.to.shared.u64 t, %1; cvt.u32.u64 %0, t; }" : "=r"(a) : "l"(p));
    return a;
}
__device__ __forceinline__ float ftf32(float x) {
    uint32_t r; asm("cvt.rna.tf32.f32 %0, %1;" : "=r"(r) : "f"(x));
    return __uint_as_float(r);
}
__device__ __forceinline__ uint64_t mkdesc(uint32_t addr) {
    const uint64_t base = (2ull << 61) | (1ull << 46) | (64ull << 32) | (1ull << 16);
    return base | ((uint64_t)(addr >> 4) & 0x3FFF);
}
__device__ __forceinline__ void mbar_init(uint32_t a, uint32_t cnt) {
    asm volatile("mbarrier.init.shared.b64 [%0], %1;" :: "r"(a), "r"(cnt) : "memory");
}
__device__ __forceinline__ void mbar_arrive(uint32_t a) {
    asm volatile("mbarrier.arrive.shared.b64 _, [%0];" :: "r"(a) : "memory");
}
__device__ __forceinline__ void mbar_wait(uint32_t a, uint32_t par) {
    uint32_t done;
    asm volatile(
        "{\n\t.reg .pred p;\n\t"
        "mbarrier.try_wait.parity.acquire.cta.shared::cta.b64 p, [%1], %2;\n\t"
        "selp.b32 %0, 1, 0, p;\n\t}"
        : "=r"(done) : "r"(a), "r"(par) : "memory");
    if (!done) {
        asm volatile(
            "{\n\t.reg .pred P1;\n\t"
            "W%=:\n\t"
            "mbarrier.try_wait.parity.acquire.cta.shared::cta.b64 P1, [%0], %1, 0x989680;\n\t"
            "@P1 bra.uni D%=;\n\t"
            "bra.uni W%=;\n\t"
            "D%=:\n\t}"
            :: "r"(a), "r"(par) : "memory");
    }
}

#if HAS_TCGEN05
__device__ __forceinline__ void mma_tf32(uint32_t d, uint64_t ad, uint64_t bd, bool acc) {
    uint32_t e = acc ? 1u : 0u, z = 0u;
    asm volatile(
        "{\n\t.reg .pred p;\n\tsetp.ne.u32 p, %5, 0;\n\t"
        "tcgen05.mma.cta_group::1.kind::tf32 [%0], %1, %2, %3, {%4,%4,%4,%4}, p;\n\t}"
        :: "r"(d), "l"(ad), "l"(bd), "r"(IDESC), "r"(z), "r"(e) : "memory");
}
__device__ __forceinline__ void mma_commit(uint32_t mbar) {
    asm volatile(
        "tcgen05.commit.cta_group::1.mbarrier::arrive::one.shared::cluster.b64 [%0];"
        :: "r"(mbar) : "memory");
}
__device__ __forceinline__ void ldtm32(uint32_t* r, uint32_t ta) {
    asm volatile(
        "tcgen05.ld.sync.aligned.32x32b.x32.b32 "
        "{%0,%1,%2,%3,%4,%5,%6,%7,%8,%9,%10,%11,%12,%13,%14,%15,"
        "%16,%17,%18,%19,%20,%21,%22,%23,%24,%25,%26,%27,%28,%29,%30,%31}, [%32];"
        : "=r"(r[0]),"=r"(r[1]),"=r"(r[2]),"=r"(r[3]),"=r"(r[4]),"=r"(r[5]),"=r"(r[6]),"=r"(r[7]),
          "=r"(r[8]),"=r"(r[9]),"=r"(r[10]),"=r"(r[11]),"=r"(r[12]),"=r"(r[13]),"=r"(r[14]),"=r"(r[15]),
          "=r"(r[16]),"=r"(r[17]),"=r"(r[18]),"=r"(r[19]),"=r"(r[20]),"=r"(r[21]),"=r"(r[22]),"=r"(r[23]),
          "=r"(r[24]),"=r"(r[25]),"=r"(r[26]),"=r"(r[27]),"=r"(r[28]),"=r"(r[29]),"=r"(r[30]),"=r"(r[31])
        : "r"(ta));
}
#endif

// ---------------- fused prep: pad/transpose (blocks 0..527) + wk/coef (blocks 528..1103) ---
__global__ __launch_bounds__(256) void prep_kernel(const float* __restrict__ x,
                                                   const float* __restrict__ w,
                                                   const float* __restrict__ off) {
    __shared__ float ts[64 * 65];
    int bk  = blockIdx.x;
    int tid = threadIdx.x;
    if (bk < 528) {
        int half = bk & 1, ri = bk >> 1;
        int hp = ri % HPAD, b = ri / HPAD;
        bool irow = (hp >= 1 && hp <= 64);
        if (irow) {
            const float* xr = x + ((size_t)(b * CIN + half * 64)) * 4096 + (size_t)(hp - 1) * 64;
            #pragma unroll
            for (int i = 0; i < 16; i++) {
                int idx = tid + i * 256;
                int c = idx >> 6, wp = idx & 63;
                ts[c * 65 + wp] = xr[(size_t)c * 4096 + wp];
            }
        }
        __syncthreads();
        float* orow = g_xpad + ((size_t)(b * HPAD + hp)) * HPAD * CIN + half * 64;
        #pragma unroll
        for (int i = 0; i < 5; i++) {
            int idx = tid + i * 256;            // over 66*16 = 1056 float4
            if (idx >= 1056) break;
            int wp = idx >> 4, c4i = idx & 15;
            float4 v = make_float4(0.f, 0.f, 0.f, 0.f);
            if (irow && wp >= 1 && wp <= 64) {
                int c = c4i * 4, wq = wp - 1;
                v = make_float4(ts[c * 65 + wq], ts[(c + 1) * 65 + wq],
                                ts[(c + 2) * 65 + wq], ts[(c + 3) * 65 + wq]);
            }
            *(float4*)(orow + (size_t)wp * CIN + c4i * 4) = v;
        }
    } else {
        int t = (bk - 528) * 256 + tid;
        {   // weight: [n][oc][c] <- w[oc][c][n]
            int c  = t & 127;
            int oc = (t >> 7) & 127;
            int n  = t >> 14;
            g_wk2[(n * OC + oc) * CIN + c] = ftf32(w[(oc * CIN + c) * 9 + n]);
        }
        {   // coefs
            int pix = t & 4095;
            int n   = (t >> 12) % 9;
            int b   = t / (9 * 4096);
            int i   = pix >> 6, j = pix & 63;
            float ox = off[(b * 18 + 2 * n)     * HW + pix];
            float oy = off[(b * 18 + 2 * n + 1) * HW + pix];
            float px = (float)(i + n / 3) + ox;
            float py = (float)(j + n % 3) + oy;
            float fx = floorf(px), fy = floorf(py);
            int qltx = min(max((int)fx, 0), 65);
            int qlty = min(max((int)fy, 0), 65);
            int qrbx = min(max((int)fx + 1, 0), 65);
            int qrby = min(max((int)fy + 1, 0), 65);
            if (px < 1.f || px > 64.f) px = fx;
            if (py < 1.f || py > 64.f) py = fy;
            px = fminf(fmaxf(px, 0.f), 65.f);
            py = fminf(fmaxf(py, 0.f), 65.f);
            float dltx = 1.f + (float)qltx - px;
            float dlty = 1.f + (float)qlty - py;
            float drbx = 1.f - ((float)qrbx - px);
            float drby = 1.f - ((float)qrby - py);
            g_gw[t] = make_float4(dltx * dlty, drbx * drby, dltx * drby, drbx * dlty);
            g_gi[t] = make_int4(qltx * HPAD + qlty, qrbx * HPAD + qrby,
                                qltx * HPAD + qrby, qrbx * HPAD + qlty);
        }
    }
}

// ------- main: software-pipelined gather + tcgen05 TF32 GEMM (4-stage ring) -------
__global__ __launch_bounds__(544, 1) void main_kernel(float* __restrict__ out) {
#if HAS_TCGEN05
    extern __shared__ char sm[];
    uint32_t smb = smem_u32(sm);
    int tid  = threadIdx.x;
    int wid  = tid >> 5;
    int lane = tid & 31;
    int b       = blockIdx.x >> 5;
    int pixbase = (blockIdx.x & 31) << 7;

    if (wid == 0)
        asm volatile("tcgen05.alloc.cta_group::1.sync.aligned.shared::cta.b32 [%0], %1;"
                     :: "r"(smb + SM_TPTR), "r"((uint32_t)TMEM_COLS) : "memory");
    if (tid == 0) {
        #pragma unroll
        for (int s = 0; s < STAGES; s++) {
            mbar_init(smb + SM_FULL(s), 16);    // one elected arrival per builder warp
            mbar_init(smb + SM_EMPTY(s), 1);    // armed by tcgen05.commit
        }
    }
    __syncthreads();

    uint32_t tmem_base;
    asm volatile("ld.shared.b32 %0, [%1];" : "=r"(tmem_base) : "r"(smb + SM_TPTR));

    if (wid == 16) {
        // ---------------- dedicated MMA issuer warp ----------------
        if (lane == 0) {
            int s = 0;
            for (int j = 0; j < NCHUNK; j++) {
                mbar_wait(smb + SM_FULL(s), (j >> 2) & 1);
                uint64_t ad = mkdesc(smb + SM_A(s));
                uint64_t bd = mkdesc(smb + SM_B(s));
                #pragma unroll
                for (int k = 0; k < 4; k++)
                    mma_tf32(tmem_base, ad + 2 * k, bd + 2 * k, (j > 0) || (k > 0));
                mma_commit(smb + SM_EMPTY(s));
                s = (s + 1) & 3;
            }
        }
    } else {
        // ---------------- 16 builder warps, 2-deep software pipeline ----------------
        const float* xb = g_xpad + (size_t)b * HPAD * HPAD * CIN;
        int c4 = tid & 7, r0 = tid >> 3;             // c4: 16B group, r0: pixel 0..63

        float4 vb[2][8];                             // 2 prefetch register sets
        float4 cw[2][2];
        int4   ci[2][2];

#define ISSUE_B(S, O, JN) do {                                                  \
        int n_ = (JN) >> 2, cc_ = (JN) & 3;                                     \
        if (cc_ == 0) {                                                         \
            const float4* gwp_ = g_gw + ((size_t)b * NS + n_) * HW + pixbase;   \
            const int4*   gip_ = g_gi + ((size_t)b * NS + n_) * HW + pixbase;   \
            cw[S][0] = gwp_[r0];      ci[S][0] = gip_[r0];                      \
            cw[S][1] = gwp_[r0 + 64]; ci[S][1] = gip_[r0 + 64];                 \
        } else {                                                                \
            cw[S][0] = cw[O][0]; ci[S][0] = ci[O][0];                           \
            cw[S][1] = cw[O][1]; ci[S][1] = ci[O][1];                           \
        }                                                                       \
        const float* cb_ = xb + cc_ * 32 + c4 * 4;                              \
        vb[S][0] = *(const float4*)(cb_ + (size_t)ci[S][0].x * CIN);            \
        vb[S][1] = *(const float4*)(cb_ + (size_t)ci[S][0].y * CIN);            \
        vb[S][2] = *(const float4*)(cb_ + (size_t)ci[S][0].z * CIN);            \
        vb[S][3] = *(const float4*)(cb_ + (size_t)ci[S][0].w * CIN);            \
        vb[S][4] = *(const float4*)(cb_ + (size_t)ci[S][1].x * CIN);            \
        vb[S][5] = *(const float4*)(cb_ + (size_t)ci[S][1].y * CIN);            \
        vb[S][6] = *(const float4*)(cb_ + (size_t)ci[S][1].z * CIN);            \
        vb[S][7] = *(const float4*)(cb_ + (size_t)ci[S][1].w * CIN);            \
    } while (0)

#define STORE_B(S, STG) do {                                                    \
        char* Bs_ = sm + SM_B(STG);                                             \
        float4 r_, q_;                                                          \
        r_.x = ftf32(cw[S][0].x*vb[S][0].x + cw[S][0].y*vb[S][1].x + cw[S][0].z*vb[S][2].x + cw[S][0].w*vb[S][3].x); \
        r_.y = ftf32(cw[S][0].x*vb[S][0].y + cw[S][0].y*vb[S][1].y + cw[S][0].z*vb[S][2].y + cw[S][0].w*vb[S][3].y); \
        r_.z = ftf32(cw[S][0].x*vb[S][0].z + cw[S][0].y*vb[S][1].z + cw[S][0].z*vb[S][2].z + cw[S][0].w*vb[S][3].z); \
        r_.w = ftf32(cw[S][0].x*vb[S][0].w + cw[S][0].y*vb[S][1].w + cw[S][0].z*vb[S][2].w + cw[S][0].w*vb[S][3].w); \
        q_.x = ftf32(cw[S][1].x*vb[S][4].x + cw[S][1].y*vb[S][5].x + cw[S][1].z*vb[S][6].x + cw[S][1].w*vb[S][7].x); \
        q_.y = ftf32(cw[S][1].x*vb[S][4].y + cw[S][1].y*vb[S][5].y + cw[S][1].z*vb[S][6].y + cw[S][1].w*vb[S][7].y); \
        q_.z = ftf32(cw[S][1].x*vb[S][4].z + cw[S][1].y*vb[S][5].z + cw[S][1].z*vb[S][6].z + cw[S][1].w*vb[S][7].z); \
        q_.w = ftf32(cw[S][1].x*vb[S][4].w + cw[S][1].y*vb[S][5].w + cw[S][1].z*vb[S][6].w + cw[S][1].w*vb[S][7].w); \
        *(float4*)(Bs_ + SW128(r0 * 128 + c4 * 16)) = r_;                       \
        *(float4*)(Bs_ + SW128((r0 + 64) * 128 + c4 * 16)) = q_;                \
    } while (0)

#define CPA(JN, STG) do {                                                       \
        int n_ = (JN) >> 2, cc_ = (JN) & 3;                                     \
        const float* wkb_ = g_wk2 + ((size_t)n_ * OC) * CIN + cc_ * 32 + c4 * 4;\
        uint32_t d0_ = smb + SM_A(STG) + SW128(r0 * 128 + c4 * 16);             \
        uint32_t d1_ = smb + SM_A(STG) + SW128((r0 + 64) * 128 + c4 * 16);      \
        asm volatile("cp.async.cg.shared.global [%0], [%1], 16;"                \
                     :: "r"(d0_), "l"(wkb_ + (size_t)r0 * CIN) : "memory");     \
        asm volatile("cp.async.cg.shared.global [%0], [%1], 16;"                \
                     :: "r"(d1_), "l"(wkb_ + (size_t)(r0 + 64) * CIN) : "memory"); \
        asm volatile("cp.async.commit_group;" ::: "memory");                    \
    } while (0)

#define FINISH_CHUNK(S, STG) do {                                               \
        STORE_B(S, STG);                                                        \
        asm volatile("cp.async.wait_group 0;" ::: "memory");                    \
        asm volatile("fence.proxy.async.shared::cta;" ::: "memory");            \
        __syncwarp();                                                           \
        if (lane == 0) mbar_arrive(smb + SM_FULL(STG));                         \
    } while (0)

#define OWN_NEXT(JN1, STG1) do {                                                \
        if ((JN1) >= STAGES) {                                                  \
            int t_ = (JN1) >> 2;                                                \
            mbar_wait(smb + SM_EMPTY(STG1), (t_ - 1) & 1);                      \
        }                                                                       \
        CPA(JN1, STG1);                                                         \
    } while (0)

        // prologue: own stage 0 (initially free)
        CPA(0, 0);
        ISSUE_B(0, 1, 0);
        int s = 0;
        for (int jj = 0; jj < 18; jj++) {
            int j0 = 2 * jj, j1 = j0 + 1;
            int s1 = (s + 1) & 3, s2 = (s + 2) & 3;
            // --- chunk j0 (set 0) ---
            ISSUE_B(1, 0, j1);                  // prefetch j1 gathers
            OWN_NEXT(j1, s1);                   // acquire next stage + A(j1) cp.async
            FINISH_CHUNK(0, s);                 // store j0, fence, arrive
            // --- chunk j1 (set 1) ---
            if (j1 + 1 < NCHUNK) {
                ISSUE_B(0, 1, j1 + 1);          // prefetch j1+1 gathers
                OWN_NEXT(j1 + 1, s2);
            }
            FINISH_CHUNK(1, s1);
            s = s2;
        }
#undef ISSUE_B
#undef STORE_B
#undef CPA
#undef FINISH_CHUNK
#undef OWN_NEXT
    }

    // all MMAs done when last commit lands: stage 3, 9th commit -> parity 0
    mbar_wait(smb + SM_EMPTY((NCHUNK - 1) & 3), ((NCHUNK - 1) >> 2) & 1);
    asm volatile("tcgen05.fence::after_thread_sync;" ::: "memory");

    // ---- epilogue: TMEM -> smem transpose -> coalesced STG (Ts aliases ring stage 0) ----
    float* Ts = (float*)(sm + SM_TS);
    for (int cg = 0; cg < 4; cg++) {
        if (wid < 4) {
            uint32_t r[32];
            ldtm32(r, tmem_base + cg * 32);
            asm volatile("tcgen05.wait::ld.sync.aligned;" ::: "memory");
            int oc = wid * 32 + lane;
            #pragma unroll
            for (int c = 0; c < 32; c++) Ts[oc * 33 + c] = __uint_as_float(r[c]);
        }
        __syncthreads();
        if (tid < 512) {
            int ocr = tid >> 2, q8 = (tid & 3) * 8;
            const float* row = Ts + ocr * 33 + q8;
            float* op = out + ((size_t)(b * OC + ocr)) * HW + pixbase + cg * 32 + q8;
            float v0 = row[0], v1 = row[1], v2 = row[2], v3 = row[3];
            float v4 = row[4], v5 = row[5], v6 = row[6], v7 = row[7];
            *(float4*)(op)     = make_float4(v0, v1, v2, v3);
            *(float4*)(op + 4) = make_float4(v4, v5, v6, v7);
        }
        __syncthreads();
    }

    if (wid == 0) {
        asm volatile("tcgen05.relinquish_alloc_permit.cta_group::1.sync.aligned;");
        asm volatile("tcgen05.dealloc.cta_group::1.sync.aligned.b32 %0, %1;"
                     :: "r"(tmem_base), "r"((uint32_t)TMEM_COLS));
    }
#else
    (void)out;   // non-103a PTX pass: dead body; sm_103a cubin selected at runtime
#endif
}

// ---------------- launch ----------------
extern "C" void kernel_launch(void* const* d_in, const int* in_sizes, int n_in,
                              void* d_out, int out_size) {
    const float* x   = (const float*)d_in[0];
    const float* off = (const float*)d_in[1];
    const float* w   = (const float*)d_in[2];
    float* out = (float*)d_out;
    (void)in_sizes; (void)n_in; (void)out_size;

    cudaFuncSetAttribute(main_kernel, cudaFuncAttributeMaxDynamicSharedMemorySize, SM_TOTAL);

    prep_kernel<<<528 + 576, 256>>>(x, w, off);
    main_kernel<<<128, 544, SM_TOTAL>>>(out);
}

// round 8
// speedup vs baseline: 1.2721x; 1.2721x over previous
#include <cuda_runtime.h>
#include <cstdint>

#define HPAD   66
#define CIN    128
#define OC     128
#define HW     4096
#define NB     4
#define NS     9
#define NCHUNK 36
#define STAGES 4

// ---- device scratch ----
__device__ float  g_xpad[NB * HPAD * HPAD * CIN + 64];  // NHWC padded x
__device__ float  g_wk2[NS * OC * CIN];                 // [n][oc][c], tf32-rounded
__device__ float4 g_gw[NB * NS * HW];                   // bilinear weights
__device__ int4   g_gi[NB * NS * HW];                   // gather indices (66x66 plane)

// ---- dynamic smem layout (bytes) ----
#define SM_TPTR   0
#define SM_FULL(s)  (16 + 8 * (s))
#define SM_EMPTY(s) (64 + 8 * (s))
#define SM_DONE   96
#define SM_A(s)   (1024 + (s) * 32768)
#define SM_B(s)   (SM_A(s) + 16384)
#define SM_TS     1024               /* aliases stage 0: free when epilogue runs */
#define SM_TOTAL  (1024 + STAGES * 32768)

#define TMEM_COLS 128
// idesc kind::tf32: dtype=F32(1)<<4, atype=TF32(2)<<7, btype=TF32(2)<<10,
// N>>3 (16)<<17, M>>4 (8)<<24
#define IDESC 0x8200910u

#define SW128(o) ((o) ^ (((o) >> 3) & 0x70))

// Feature gate: tcgen05 only exists in the compute_103a device pass.
#if !defined(__CUDA_ARCH__) || defined(__CUDA_ARCH_FEAT_SM103_ALL)
#define HAS_TCGEN05 1
#else
#define HAS_TCGEN05 0
#endif

// ---------------- PTX helpers ----------------
__device__ __forceinline__ uint32_t smem_u32(const void* p) {
    uint32_t a;
    asm("{ .reg .u64 t; cvta.to.shared.u64 t, %1; cvt.u32.u64 %0, t; }" : "=r"(a) : "l"(p));
    return a;
}
__device__ __forceinline__ float ftf32(float x) {
    uint32_t r; asm("cvt.rna.tf32.f32 %0, %1;" : "=r"(r) : "f"(x));
    return __uint_as_float(r);
}
__device__ __forceinline__ uint64_t mkdesc(uint32_t addr) {
    const uint64_t base = (2ull << 61) | (1ull << 46) | (64ull << 32) | (1ull << 16);
    return base | ((uint64_t)(addr >> 4) & 0x3FFF);
}
__device__ __forceinline__ void mbar_init(uint32_t a, uint32_t cnt) {
    asm volatile("mbarrier.init.shared.b64 [%0], %1;" :: "r"(a), "r"(cnt) : "memory");
}
__device__ __forceinline__ void mbar_arrive(uint32_t a) {
    asm volatile("mbarrier.arrive.shared.b64 _, [%0];" :: "r"(a) : "memory");
}
__device__ __forceinline__ void mbar_wait(uint32_t a, uint32_t par) {
    uint32_t done;
    asm volatile(
        "{\n\t.reg .pred p;\n\t"
        "mbarrier.try_wait.parity.acquire.cta.shared::cta.b64 p, [%1], %2;\n\t"
        "selp.b32 %0, 1, 0, p;\n\t}"
        : "=r"(done) : "r"(a), "r"(par) : "memory");
    if (!done) {
        asm volatile(
            "{\n\t.reg .pred P1;\n\t"
            "W%=:\n\t"
            "mbarrier.try_wait.parity.acquire.cta.shared::cta.b64 P1, [%0], %1, 0x989680;\n\t"
            "@P1 bra.uni D%=;\n\t"
            "bra.uni W%=;\n\t"
            "D%=:\n\t}"
            :: "r"(a), "r"(par) : "memory");
    }
}

#if HAS_TCGEN05
__device__ __forceinline__ void mma_tf32(uint32_t d, uint64_t ad, uint64_t bd, bool acc) {
    uint32_t e = acc ? 1u : 0u, z = 0u;
    asm volatile(
        "{\n\t.reg .pred p;\n\tsetp.ne.u32 p, %5, 0;\n\t"
        "tcgen05.mma.cta_group::1.kind::tf32 [%0], %1, %2, %3, {%4,%4,%4,%4}, p;\n\t}"
        :: "r"(d), "l"(ad), "l"(bd), "r"(IDESC), "r"(z), "r"(e) : "memory");
}
__device__ __forceinline__ void mma_commit(uint32_t mbar) {
    asm volatile(
        "tcgen05.commit.cta_group::1.mbarrier::arrive::one.shared::cluster.b64 [%0];"
        :: "r"(mbar) : "memory");
}
__device__ __forceinline__ void ldtm32(uint32_t* r, uint32_t ta) {
    asm volatile(
        "tcgen05.ld.sync.aligned.32x32b.x32.b32 "
        "{%0,%1,%2,%3,%4,%5,%6,%7,%8,%9,%10,%11,%12,%13,%14,%15,"
        "%16,%17,%18,%19,%20,%21,%22,%23,%24,%25,%26,%27,%28,%29,%30,%31}, [%32];"
        : "=r"(r[0]),"=r"(r[1]),"=r"(r[2]),"=r"(r[3]),"=r"(r[4]),"=r"(r[5]),"=r"(r[6]),"=r"(r[7]),
          "=r"(r[8]),"=r"(r[9]),"=r"(r[10]),"=r"(r[11]),"=r"(r[12]),"=r"(r[13]),"=r"(r[14]),"=r"(r[15]),
          "=r"(r[16]),"=r"(r[17]),"=r"(r[18]),"=r"(r[19]),"=r"(r[20]),"=r"(r[21]),"=r"(r[22]),"=r"(r[23]),
          "=r"(r[24]),"=r"(r[25]),"=r"(r[26]),"=r"(r[27]),"=r"(r[28]),"=r"(r[29]),"=r"(r[30]),"=r"(r[31])
        : "r"(ta));
}
#endif

// ---------------- fused prep: pad/transpose (blocks 0..527) + wk/coef (blocks 528..1103) ---
__global__ __launch_bounds__(256) void prep_kernel(const float* __restrict__ x,
                                                   const float* __restrict__ w,
                                                   const float* __restrict__ off) {
    __shared__ float ts[64 * 65];
    int bk  = blockIdx.x;
    int tid = threadIdx.x;
    if (bk < 528) {
        int half = bk & 1, ri = bk >> 1;
        int hp = ri % HPAD, b = ri / HPAD;
        bool irow = (hp >= 1 && hp <= 64);
        if (irow) {
            const float* xr = x + ((size_t)(b * CIN + half * 64)) * 4096 + (size_t)(hp - 1) * 64;
            #pragma unroll
            for (int i = 0; i < 16; i++) {
                int idx = tid + i * 256;
                int c = idx >> 6, wp = idx & 63;
                ts[c * 65 + wp] = xr[(size_t)c * 4096 + wp];
            }
        }
        __syncthreads();
        float* orow = g_xpad + ((size_t)(b * HPAD + hp)) * HPAD * CIN + half * 64;
        #pragma unroll
        for (int i = 0; i < 5; i++) {
            int idx = tid + i * 256;            // over 66*16 = 1056 float4
            if (idx >= 1056) break;
            int wp = idx >> 4, c4i = idx & 15;
            float4 v = make_float4(0.f, 0.f, 0.f, 0.f);
            if (irow && wp >= 1 && wp <= 64) {
                int c = c4i * 4, wq = wp - 1;
                v = make_float4(ts[c * 65 + wq], ts[(c + 1) * 65 + wq],
                                ts[(c + 2) * 65 + wq], ts[(c + 3) * 65 + wq]);
            }
            *(float4*)(orow + (size_t)wp * CIN + c4i * 4) = v;
        }
    } else {
        int t = (bk - 528) * 256 + tid;
        {   // weight: [n][oc][c] <- w[oc][c][n]
            int c  = t & 127;
            int oc = (t >> 7) & 127;
            int n  = t >> 14;
            g_wk2[(n * OC + oc) * CIN + c] = ftf32(w[(oc * CIN + c) * 9 + n]);
        }
        {   // coefs
            int pix = t & 4095;
            int n   = (t >> 12) % 9;
            int b   = t / (9 * 4096);
            int i   = pix >> 6, j = pix & 63;
            float ox = off[(b * 18 + 2 * n)     * HW + pix];
            float oy = off[(b * 18 + 2 * n + 1) * HW + pix];
            float px = (float)(i + n / 3) + ox;
            float py = (float)(j + n % 3) + oy;
            float fx = floorf(px), fy = floorf(py);
            int qltx = min(max((int)fx, 0), 65);
            int qlty = min(max((int)fy, 0), 65);
            int qrbx = min(max((int)fx + 1, 0), 65);
            int qrby = min(max((int)fy + 1, 0), 65);
            if (px < 1.f || px > 64.f) px = fx;
            if (py < 1.f || py > 64.f) py = fy;
            px = fminf(fmaxf(px, 0.f), 65.f);
            py = fminf(fmaxf(py, 0.f), 65.f);
            float dltx = 1.f + (float)qltx - px;
            float dlty = 1.f + (float)qlty - py;
            float drbx = 1.f - ((float)qrbx - px);
            float drby = 1.f - ((float)qrby - py);
            g_gw[t] = make_float4(dltx * dlty, drbx * drby, dltx * drby, drbx * dlty);
            g_gi[t] = make_int4(qltx * HPAD + qlty, qrbx * HPAD + qrby,
                                qltx * HPAD + qrby, qrbx * HPAD + qlty);
        }
    }
}

// ------- main: warp-group-specialized gather + tcgen05 TF32 GEMM -------
// Builder groups of 4 warps; group g owns c-chunk cc=g and ring stage g.
__global__ __launch_bounds__(544, 1) void main_kernel(float* __restrict__ out) {
#if HAS_TCGEN05
    extern __shared__ char sm[];
    uint32_t smb = smem_u32(sm);
    int tid  = threadIdx.x;
    int wid  = tid >> 5;
    int lane = tid & 31;
    int b       = blockIdx.x >> 5;
    int pixbase = (blockIdx.x & 31) << 7;

    if (wid == 0)
        asm volatile("tcgen05.alloc.cta_group::1.sync.aligned.shared::cta.b32 [%0], %1;"
                     :: "r"(smb + SM_TPTR), "r"((uint32_t)TMEM_COLS) : "memory");
    if (tid == 0) {
        #pragma unroll
        for (int s = 0; s < STAGES; s++) {
            mbar_init(smb + SM_FULL(s), 4);     // 4 warps per builder group
            mbar_init(smb + SM_EMPTY(s), 1);    // armed by tcgen05.commit
        }
        mbar_init(smb + SM_DONE, 1);            // single-phase completion
    }
    __syncthreads();

    uint32_t tmem_base;
    asm volatile("ld.shared.b32 %0, [%1];" : "=r"(tmem_base) : "r"(smb + SM_TPTR));

    if (wid == 16) {
        // ---------------- dedicated MMA issuer warp ----------------
        if (lane == 0) {
            for (int j = 0; j < NCHUNK; j++) {
                int s = j & 3;
                mbar_wait(smb + SM_FULL(s), (j >> 2) & 1);
                uint64_t ad = mkdesc(smb + SM_A(s));
                uint64_t bd = mkdesc(smb + SM_B(s));
                #pragma unroll
                for (int k = 0; k < 4; k++)
                    mma_tf32(tmem_base, ad + 2 * k, bd + 2 * k, (j > 0) || (k > 0));
                mma_commit(smb + SM_EMPTY(s));
            }
            mma_commit(smb + SM_DONE);          // arrives when ALL prior MMAs done
        }
    } else {
        // ---------------- builder group g: chunks j = 4n + g, stage g ----------------
        int g    = wid >> 2;
        int gtid = (wid & 3) * 32 + lane;       // 0..127 within group
        int c4   = gtid & 7;                    // 16B column group
        int r0   = gtid >> 3;                   // 0..15 -> pixels r0 + 16k

        const float* xb = g_xpad + (size_t)b * HPAD * HPAD * CIN;
        const float* cb = xb + g * 32 + c4 * 4;
        char* Bs = sm + SM_B(g);
        uint32_t fullb  = smb + SM_FULL(g);
        uint32_t emptyb = smb + SM_EMPTY(g);

        for (int n = 0; n < NS; n++) {
            if (n >= 1) mbar_wait(emptyb, (n - 1) & 1);

            // ---- A tile (128 oc x 32 ch) via cp.async ----
            {
                const float* wkb = g_wk2 + ((size_t)n * OC) * CIN + g * 32 + c4 * 4;
                #pragma unroll
                for (int k = 0; k < 8; k++) {
                    int oc = r0 + k * 16;
                    uint32_t d = smb + SM_A(g) + SW128(oc * 128 + c4 * 16);
                    asm volatile("cp.async.cg.shared.global [%0], [%1], 16;"
                                 :: "r"(d), "l"(wkb + (size_t)oc * CIN) : "memory");
                }
                asm volatile("cp.async.commit_group;" ::: "memory");
            }

            // ---- B tile: 8 pixels per thread, 2 at a time ----
            const float4* gwp = g_gw + ((size_t)b * NS + n) * HW + pixbase;
            const int4*   gip = g_gi + ((size_t)b * NS + n) * HW + pixbase;
            #pragma unroll
            for (int pb = 0; pb < 4; pb++) {
                int p0 = r0 + pb * 32, p1 = p0 + 16;
                float4 w0 = gwp[p0]; int4 i0 = gip[p0];
                float4 w1 = gwp[p1]; int4 i1 = gip[p1];
                float4 v0 = *(const float4*)(cb + (size_t)i0.x * CIN);
                float4 v1 = *(const float4*)(cb + (size_t)i0.y * CIN);
                float4 v2 = *(const float4*)(cb + (size_t)i0.z * CIN);
                float4 v3 = *(const float4*)(cb + (size_t)i0.w * CIN);
                float4 u0 = *(const float4*)(cb + (size_t)i1.x * CIN);
                float4 u1 = *(const float4*)(cb + (size_t)i1.y * CIN);
                float4 u2 = *(const float4*)(cb + (size_t)i1.z * CIN);
                float4 u3 = *(const float4*)(cb + (size_t)i1.w * CIN);
                float4 r_, q_;
                r_.x = ftf32(w0.x*v0.x + w0.y*v1.x + w0.z*v2.x + w0.w*v3.x);
                r_.y = ftf32(w0.x*v0.y + w0.y*v1.y + w0.z*v2.y + w0.w*v3.y);
                r_.z = ftf32(w0.x*v0.z + w0.y*v1.z + w0.z*v2.z + w0.w*v3.z);
                r_.w = ftf32(w0.x*v0.w + w0.y*v1.w + w0.z*v2.w + w0.w*v3.w);
                q_.x = ftf32(w1.x*u0.x + w1.y*u1.x + w1.z*u2.x + w1.w*u3.x);
                q_.y = ftf32(w1.x*u0.y + w1.y*u1.y + w1.z*u2.y + w1.w*u3.y);
                q_.z = ftf32(w1.x*u0.z + w1.y*u1.z + w1.z*u2.z + w1.w*u3.z);
                q_.w = ftf32(w1.x*u0.w + w1.y*u1.w + w1.z*u2.w + w1.w*u3.w);
                *(float4*)(Bs + SW128(p0 * 128 + c4 * 16)) = r_;
                *(float4*)(Bs + SW128(p1 * 128 + c4 * 16)) = q_;
            }

            asm volatile("cp.async.wait_group 0;" ::: "memory");
            asm volatile("fence.proxy.async.shared::cta;" ::: "memory");
            __syncwarp();
            if (lane == 0) mbar_arrive(fullb);
        }
    }

    // single-phase completion barrier (no parity wrap ambiguity)
    mbar_wait(smb + SM_DONE, 0);
    asm volatile("tcgen05.fence::after_thread_sync;" ::: "memory");

    // ---- epilogue: TMEM -> smem transpose -> coalesced STG (Ts aliases ring stage 0) ----
    float* Ts = (float*)(sm + SM_TS);
    for (int cg = 0; cg < 4; cg++) {
        if (wid < 4) {
            uint32_t r[32];
            ldtm32(r, tmem_base + cg * 32);
            asm volatile("tcgen05.wait::ld.sync.aligned;" ::: "memory");
            int oc = wid * 32 + lane;
            #pragma unroll
            for (int c = 0; c < 32; c++) Ts[oc * 33 + c] = __uint_as_float(r[c]);
        }
        __syncthreads();
        if (tid < 512) {
            int ocr = tid >> 2, q8 = (tid & 3) * 8;
            const float* row = Ts + ocr * 33 + q8;
            float* op = out + ((size_t)(b * OC + ocr)) * HW + pixbase + cg * 32 + q8;
            float v0 = row[0], v1 = row[1], v2 = row[2], v3 = row[3];
            float v4 = row[4], v5 = row[5], v6 = row[6], v7 = row[7];
            *(float4*)(op)     = make_float4(v0, v1, v2, v3);
            *(float4*)(op + 4) = make_float4(v4, v5, v6, v7);
        }
        __syncthreads();
    }

    if (wid == 0) {
        asm volatile("tcgen05.relinquish_alloc_permit.cta_group::1.sync.aligned;");
        asm volatile("tcgen05.dealloc.cta_group::1.sync.aligned.b32 %0, %1;"
                     :: "r"(tmem_base), "r"((uint32_t)TMEM_COLS));
    }
#else
    (void)out;   // non-103a PTX pass: dead body; sm_103a cubin selected at runtime
#endif
}

// ---------------- launch ----------------
extern "C" void kernel_launch(void* const* d_in, const int* in_sizes, int n_in,
                              void* d_out, int out_size) {
    const float* x   = (const float*)d_in[0];
    const float* off = (const float*)d_in[1];
    const float* w   = (const float*)d_in[2];
    float* out = (float*)d_out;
    (void)in_sizes; (void)n_in; (void)out_size;

    cudaFuncSetAttribute(main_kernel, cudaFuncAttributeMaxDynamicSharedMemorySize, SM_TOTAL);

    prep_kernel<<<528 + 576, 256>>>(x, w, off);
    main_kernel<<<128, 544, SM_TOTAL>>>(out);
}

// round 9
// speedup vs baseline: 1.4309x; 1.1249x over previous
#include <cuda_runtime.h>
#include <cstdint>

#define HPAD   66
#define CIN    128
#define OC     128
#define HW     4096
#define NB     4
#define NS     9
#define NCHUNK 36
#define STAGES 4

// ---- device scratch ----
__device__ float  g_xpad[NB * HPAD * HPAD * CIN + 64];  // NHWC padded x
__device__ float  g_wk2[NS * OC * CIN];                 // [n][oc][c], tf32-rounded
__device__ float4 g_gw[NB * NS * HW];                   // bilinear weights
__device__ int4   g_gi[NB * NS * HW];                   // gather indices (66x66 plane)

// ---- dynamic smem layout (bytes) ----
#define SM_TPTR   0
#define SM_FULL(s)  (16 + 8 * (s))
#define SM_EMPTY(s) (64 + 8 * (s))
#define SM_A(s)   (1024 + (s) * 32768)
#define SM_B(s)   (SM_A(s) + 16384)
#define SM_TS     1024               /* aliases ring stage 0: free when epilogue runs */
#define SM_TOTAL  (1024 + STAGES * 32768)

#define TMEM_COLS 128
// idesc kind::tf32: dtype=F32(1)<<4, atype=TF32(2)<<7, btype=TF32(2)<<10,
// N>>3 (16)<<17, M>>4 (8)<<24
#define IDESC 0x8200910u

#define SW128(o) ((o) ^ (((o) >> 3) & 0x70))

// Feature gate: tcgen05 only exists in the compute_103a device pass.
#if !defined(__CUDA_ARCH__) || defined(__CUDA_ARCH_FEAT_SM103_ALL)
#define HAS_TCGEN05 1
#else
#define HAS_TCGEN05 0
#endif

// ---------------- PTX helpers ----------------
__device__ __forceinline__ uint32_t smem_u32(const void* p) {
    uint32_t a;
    asm("{ .reg .u64 t; cvta.to.shared.u64 t, %1; cvt.u32.u64 %0, t; }" : "=r"(a) : "l"(p));
    return a;
}
__device__ __forceinline__ float ftf32(float x) {
    uint32_t r; asm("cvt.rna.tf32.f32 %0, %1;" : "=r"(r) : "f"(x));
    return __uint_as_float(r);
}
__device__ __forceinline__ uint64_t mkdesc(uint32_t addr) {
    const uint64_t base = (2ull << 61) | (1ull << 46) | (64ull << 32) | (1ull << 16);
    return base | ((uint64_t)(addr >> 4) & 0x3FFF);
}
__device__ __forceinline__ void mbar_init(uint32_t a, uint32_t cnt) {
    asm volatile("mbarrier.init.shared.b64 [%0], %1;" :: "r"(a), "r"(cnt) : "memory");
}
__device__ __forceinline__ void mbar_arrive(uint32_t a) {
    asm volatile("mbarrier.arrive.shared.b64 _, [%0];" :: "r"(a) : "memory");
}
__device__ __forceinline__ void mbar_wait(uint32_t a, uint32_t par) {
    uint32_t done;
    asm volatile(
        "{\n\t.reg .pred p;\n\t"
        "mbarrier.try_wait.parity.acquire.cta.shared::cta.b64 p, [%1], %2;\n\t"
        "selp.b32 %0, 1, 0, p;\n\t}"
        : "=r"(done) : "r"(a), "r"(par) : "memory");
    if (!done) {
        asm volatile(
            "{\n\t.reg .pred P1;\n\t"
            "W%=:\n\t"
            "mbarrier.try_wait.parity.acquire.cta.shared::cta.b64 P1, [%0], %1, 0x989680;\n\t"
            "@P1 bra.uni D%=;\n\t"
            "bra.uni W%=;\n\t"
            "D%=:\n\t}"
            :: "r"(a), "r"(par) : "memory");
    }
}

#if HAS_TCGEN05
__device__ __forceinline__ void mma_tf32(uint32_t d, uint64_t ad, uint64_t bd, bool acc) {
    uint32_t e = acc ? 1u : 0u, z = 0u;
    asm volatile(
        "{\n\t.reg .pred p;\n\tsetp.ne.u32 p, %5, 0;\n\t"
        "tcgen05.mma.cta_group::1.kind::tf32 [%0], %1, %2, %3, {%4,%4,%4,%4}, p;\n\t}"
        :: "r"(d), "l"(ad), "l"(bd), "r"(IDESC), "r"(z), "r"(e) : "memory");
}
__device__ __forceinline__ void mma_commit(uint32_t mbar) {
    asm volatile(
        "tcgen05.commit.cta_group::1.mbarrier::arrive::one.shared::cluster.b64 [%0];"
        :: "r"(mbar) : "memory");
}
__device__ __forceinline__ void ldtm32(uint32_t* r, uint32_t ta) {
    asm volatile(
        "tcgen05.ld.sync.aligned.32x32b.x32.b32 "
        "{%0,%1,%2,%3,%4,%5,%6,%7,%8,%9,%10,%11,%12,%13,%14,%15,"
        "%16,%17,%18,%19,%20,%21,%22,%23,%24,%25,%26,%27,%28,%29,%30,%31}, [%32];"
        : "=r"(r[0]),"=r"(r[1]),"=r"(r[2]),"=r"(r[3]),"=r"(r[4]),"=r"(r[5]),"=r"(r[6]),"=r"(r[7]),
          "=r"(r[8]),"=r"(r[9]),"=r"(r[10]),"=r"(r[11]),"=r"(r[12]),"=r"(r[13]),"=r"(r[14]),"=r"(r[15]),
          "=r"(r[16]),"=r"(r[17]),"=r"(r[18]),"=r"(r[19]),"=r"(r[20]),"=r"(r[21]),"=r"(r[22]),"=r"(r[23]),
          "=r"(r[24]),"=r"(r[25]),"=r"(r[26]),"=r"(r[27]),"=r"(r[28]),"=r"(r[29]),"=r"(r[30]),"=r"(r[31])
        : "r"(ta));
}
#endif

// ---------------- fused prep: pad/transpose (blocks 0..527) + wk/coef (blocks 528..1103) ---
__global__ __launch_bounds__(256) void prep_kernel(const float* __restrict__ x,
                                                   const float* __restrict__ w,
                                                   const float* __restrict__ off) {
    __shared__ float ts[64 * 65];
    int bk  = blockIdx.x;
    int tid = threadIdx.x;
    if (bk < 528) {
        int half = bk & 1, ri = bk >> 1;
        int hp = ri % HPAD, b = ri / HPAD;
        bool irow = (hp >= 1 && hp <= 64);
        if (irow) {
            const float* xr = x + ((size_t)(b * CIN + half * 64)) * 4096 + (size_t)(hp - 1) * 64;
            #pragma unroll
            for (int i = 0; i < 16; i++) {
                int idx = tid + i * 256;
                int c = idx >> 6, wp = idx & 63;
                ts[c * 65 + wp] = xr[(size_t)c * 4096 + wp];
            }
        }
        __syncthreads();
        float* orow = g_xpad + ((size_t)(b * HPAD + hp)) * HPAD * CIN + half * 64;
        #pragma unroll
        for (int i = 0; i < 5; i++) {
            int idx = tid + i * 256;            // over 66*16 = 1056 float4
            if (idx >= 1056) break;
            int wp = idx >> 4, c4i = idx & 15;
            float4 v = make_float4(0.f, 0.f, 0.f, 0.f);
            if (irow && wp >= 1 && wp <= 64) {
                int c = c4i * 4, wq = wp - 1;
                v = make_float4(ts[c * 65 + wq], ts[(c + 1) * 65 + wq],
                                ts[(c + 2) * 65 + wq], ts[(c + 3) * 65 + wq]);
            }
            *(float4*)(orow + (size_t)wp * CIN + c4i * 4) = v;
        }
    } else {
        int t = (bk - 528) * 256 + tid;
        {   // weight: [n][oc][c] <- w[oc][c][n]
            int c  = t & 127;
            int oc = (t >> 7) & 127;
            int n  = t >> 14;
            g_wk2[(n * OC + oc) * CIN + c] = ftf32(w[(oc * CIN + c) * 9 + n]);
        }
        {   // coefs
            int pix = t & 4095;
            int n   = (t >> 12) % 9;
            int b   = t / (9 * 4096);
            int i   = pix >> 6, j = pix & 63;
            float ox = off[(b * 18 + 2 * n)     * HW + pix];
            float oy = off[(b * 18 + 2 * n + 1) * HW + pix];
            float px = (float)(i + n / 3) + ox;
            float py = (float)(j + n % 3) + oy;
            float fx = floorf(px), fy = floorf(py);
            int qltx = min(max((int)fx, 0), 65);
            int qlty = min(max((int)fy, 0), 65);
            int qrbx = min(max((int)fx + 1, 0), 65);
            int qrby = min(max((int)fy + 1, 0), 65);
            if (px < 1.f || px > 64.f) px = fx;
            if (py < 1.f || py > 64.f) py = fy;
            px = fminf(fmaxf(px, 0.f), 65.f);
            py = fminf(fmaxf(py, 0.f), 65.f);
            float dltx = 1.f + (float)qltx - px;
            float dlty = 1.f + (float)qlty - py;
            float drbx = 1.f - ((float)qrbx - px);
            float drby = 1.f - ((float)qrby - py);
            g_gw[t] = make_float4(dltx * dlty, drbx * drby, dltx * drby, drbx * dlty);
            g_gi[t] = make_int4(qltx * HPAD + qlty, qrbx * HPAD + qrby,
                                qltx * HPAD + qrby, qrbx * HPAD + qlty);
        }
    }
}

// ------- main: two builder sets on alternating chunks + tcgen05 TF32 GEMM -------
__global__ __launch_bounds__(544, 1) void main_kernel(float* __restrict__ out) {
#if HAS_TCGEN05
    extern __shared__ char sm[];
    uint32_t smb = smem_u32(sm);
    int tid  = threadIdx.x;
    int wid  = tid >> 5;
    int lane = tid & 31;
    int b       = blockIdx.x >> 5;
    int pixbase = (blockIdx.x & 31) << 7;

    if (wid == 0)
        asm volatile("tcgen05.alloc.cta_group::1.sync.aligned.shared::cta.b32 [%0], %1;"
                     :: "r"(smb + SM_TPTR), "r"((uint32_t)TMEM_COLS) : "memory");
    if (tid == 0) {
        #pragma unroll
        for (int s = 0; s < STAGES; s++) {
            mbar_init(smb + SM_FULL(s), 8);     // one elected arrival per builder warp of a set
            mbar_init(smb + SM_EMPTY(s), 1);    // armed by tcgen05.commit
        }
    }
    __syncthreads();

    uint32_t tmem_base;
    asm volatile("ld.shared.b32 %0, [%1];" : "=r"(tmem_base) : "r"(smb + SM_TPTR));

    if (wid == 16) {
        // ---------------- dedicated MMA issuer warp ----------------
        if (lane == 0) {
            for (int j = 0; j < NCHUNK; j++) {
                int s = j & 3;
                mbar_wait(smb + SM_FULL(s), (j >> 2) & 1);
                uint64_t ad = mkdesc(smb + SM_A(s));
                uint64_t bd = mkdesc(smb + SM_B(s));
                #pragma unroll
                for (int k = 0; k < 4; k++)
                    mma_tf32(tmem_base, ad + 2 * k, bd + 2 * k, (j > 0) || (k > 0));
                mma_commit(smb + SM_EMPTY(s));
            }
        }
    } else {
        // ---- builder set (8 warps each): set 0 -> even chunks, set 1 -> odd chunks ----
        int setid = wid >> 3;                   // 0 or 1
        int gtid  = (wid & 7) * 32 + lane;      // 0..255 within set
        int c4    = gtid & 7;                   // 16B channel group
        int r0    = gtid >> 3;                  // 0..31 -> pixels r0 + 32k

        const float* xb = g_xpad + (size_t)b * HPAD * HPAD * CIN;
        float4 cw[4]; int4 ci[4];               // coef cache for 4 pixels (one n)

        #pragma unroll 2
        for (int m = 0; m < 18; m++) {
            int j  = 2 * m + setid;
            int n  = j >> 2, cc = j & 3, s = cc;
            uint32_t emptyb = smb + SM_EMPTY(s);
            uint32_t fullb  = smb + SM_FULL(s);

            if (j >= 4) mbar_wait(emptyb, ((j >> 2) - 1) & 1);

            // ---- A tile via cp.async (own-chunk group only) ----
            {
                const float* wkb = g_wk2 + ((size_t)n * OC) * CIN + cc * 32 + c4 * 4;
                #pragma unroll
                for (int k = 0; k < 4; k++) {
                    int oc = r0 + 32 * k;
                    uint32_t d = smb + SM_A(s) + SW128(oc * 128 + c4 * 16);
                    asm volatile("cp.async.cg.shared.global [%0], [%1], 16;"
                                 :: "r"(d), "l"(wkb + (size_t)oc * CIN) : "memory");
                }
                asm volatile("cp.async.commit_group;" ::: "memory");
            }

            // ---- coefs: reload on first chunk of each n for this set ----
            if (((j >> 1) & 1) == 0) {
                const float4* gwp = g_gw + ((size_t)b * NS + n) * HW + pixbase;
                const int4*   gip = g_gi + ((size_t)b * NS + n) * HW + pixbase;
                #pragma unroll
                for (int k = 0; k < 4; k++) {
                    cw[k] = gwp[r0 + 32 * k];
                    ci[k] = gip[r0 + 32 * k];
                }
            }

            // ---- B tile: 4 pixels, 16 independent gathers ----
            char* Bs = sm + SM_B(s);
            const float* cb = xb + cc * 32 + c4 * 4;
            #pragma unroll
            for (int k = 0; k < 4; k++) {
                int p = r0 + 32 * k;
                float4 v0 = *(const float4*)(cb + (size_t)ci[k].x * CIN);
                float4 v1 = *(const float4*)(cb + (size_t)ci[k].y * CIN);
                float4 v2 = *(const float4*)(cb + (size_t)ci[k].z * CIN);
                float4 v3 = *(const float4*)(cb + (size_t)ci[k].w * CIN);
                float4 r_;
                r_.x = ftf32(cw[k].x*v0.x + cw[k].y*v1.x + cw[k].z*v2.x + cw[k].w*v3.x);
                r_.y = ftf32(cw[k].x*v0.y + cw[k].y*v1.y + cw[k].z*v2.y + cw[k].w*v3.y);
                r_.z = ftf32(cw[k].x*v0.z + cw[k].y*v1.z + cw[k].z*v2.z + cw[k].w*v3.z);
                r_.w = ftf32(cw[k].x*v0.w + cw[k].y*v1.w + cw[k].z*v2.w + cw[k].w*v3.w);
                *(float4*)(Bs + SW128(p * 128 + c4 * 16)) = r_;
            }

            asm volatile("cp.async.wait_group 0;" ::: "memory");
            asm volatile("fence.proxy.async.shared::cta;" ::: "memory");
            __syncwarp();
            if (lane == 0) mbar_arrive(fullb);
        }
    }

    // last chunk (j=35) uses stage 3; its commit is the 9th completion of empty[3]:
    // wait for phase parity (35>>2)&1 = 0. MMAs complete in order, so all are done.
    mbar_wait(smb + SM_EMPTY(3), ((NCHUNK - 1) >> 2) & 1);
    asm volatile("tcgen05.fence::after_thread_sync;" ::: "memory");

    // ---- epilogue: TMEM -> smem transpose -> coalesced STG (Ts aliases ring stage 0) ----
    float* Ts = (float*)(sm + SM_TS);
    for (int cg = 0; cg < 4; cg++) {
        if (wid < 4) {
            uint32_t r[32];
            ldtm32(r, tmem_base + cg * 32);
            asm volatile("tcgen05.wait::ld.sync.aligned;" ::: "memory");
            int oc = wid * 32 + lane;
            #pragma unroll
            for (int c = 0; c < 32; c++) Ts[oc * 33 + c] = __uint_as_float(r[c]);
        }
        __syncthreads();
        if (tid < 512) {
            int ocr = tid >> 2, q8 = (tid & 3) * 8;
            const float* row = Ts + ocr * 33 + q8;
            float* op = out + ((size_t)(b * OC + ocr)) * HW + pixbase + cg * 32 + q8;
            float v0 = row[0], v1 = row[1], v2 = row[2], v3 = row[3];
            float v4 = row[4], v5 = row[5], v6 = row[6], v7 = row[7];
            *(float4*)(op)     = make_float4(v0, v1, v2, v3);
            *(float4*)(op + 4) = make_float4(v4, v5, v6, v7);
        }
        __syncthreads();
    }

    if (wid == 0) {
        asm volatile("tcgen05.relinquish_alloc_permit.cta_group::1.sync.aligned;");
        asm volatile("tcgen05.dealloc.cta_group::1.sync.aligned.b32 %0, %1;"
                     :: "r"(tmem_base), "r"((uint32_t)TMEM_COLS));
    }
#else
    (void)out;   // non-103a PTX pass: dead body; sm_103a cubin selected at runtime
#endif
}

// ---------------- launch ----------------
extern "C" void kernel_launch(void* const* d_in, const int* in_sizes, int n_in,
                              void* d_out, int out_size) {
    const float* x   = (const float*)d_in[0];
    const float* off = (const float*)d_in[1];
    const float* w   = (const float*)d_in[2];
    float* out = (float*)d_out;
    (void)in_sizes; (void)n_in; (void)out_size;

    cudaFuncSetAttribute(main_kernel, cudaFuncAttributeMaxDynamicSharedMemorySize, SM_TOTAL);

    prep_kernel<<<528 + 576, 256>>>(x, w, off);
    main_kernel<<<128, 544, SM_TOTAL>>>(out);
}